// round 2
// baseline (speedup 1.0000x reference)
#include <cuda_runtime.h>

// Problem constants (fixed by the dataset)
//   B=131072, IN_DIM=128, N_NODES=511, N_LEAVES=512, N_ACTIONS=16
#define TM        32                    // rows per block
#define KS        8                     // node (k) slice per W2 stage
#define WS_STRIDE 516                   // padded leaf-stride (mult of 4, bank-skewed)
#define WS_HALF   (KS * WS_STRIDE)      // 4128 floats per half
#define HT_FLOATS (512 * TM)            // 16384 floats (node 511 zero-padded)
#define POOL_OFF  (HT_FLOATS + 2 * WS_HALF)   // 24640
#define SMEM_FLOATS (POOL_OFF + TM * 16)      // 25152
#define SMEM_BYTES  (SMEM_FLOATS * 4)         // 100608 B -> 2 CTAs/SM

// order-preserving float<->uint for atomicMax-based segment max
__device__ __forceinline__ unsigned ford(float f) {
    unsigned u = __float_as_uint(f);
    return (u & 0x80000000u) ? ~u : (u | 0x80000000u);
}
__device__ __forceinline__ float funord(unsigned s) {
    return __uint_as_float((s & 0x80000000u) ? (s ^ 0x80000000u) : ~s);
}

__global__ __launch_bounds__(256, 2)
void dtnet_fused_kernel(const float* __restrict__ x,
                        const float* __restrict__ W1,
                        const float* __restrict__ b1,
                        const float* __restrict__ W2,
                        const int*   __restrict__ leaf_actions,
                        float*       __restrict__ out)
{
    extern __shared__ float sm[];
    float*    ht   = sm;                          // [512 nodes][32 rows]
    float*    ws   = sm + HT_FLOATS;              // staged W2 slice (2 halves)
    unsigned* pool = (unsigned*)(sm + POOL_OFF);  // [32 rows][16 actions]
    float*    xs   = ws;                          // phase-1 scratch (128*33 = 4224 <= 8256)

    const int tid  = threadIdx.x;
    const int row0 = blockIdx.x * TM;

    // ---- init action-max pool (ford encoding: 0 < ord(-inf), so 0 is safe bottom)
    for (int i = tid; i < TM * 16; i += 256) pool[i] = 0u;

    // ---- stage x tile transposed: xs[k*33 + r]
    {
        const float4* xg = (const float4*)(x + (size_t)row0 * 128);
        for (int i = tid; i < TM * 32; i += 256) {
            int r  = i >> 5;
            int k4 = i & 31;
            float4 v = xg[r * 32 + k4];
            int k = k4 * 4;
            xs[(k + 0) * 33 + r] = v.x;
            xs[(k + 1) * 33 + r] = v.y;
            xs[(k + 2) * 33 + r] = v.z;
            xs[(k + 3) * 33 + r] = v.w;
        }
    }
    __syncthreads();

    // ---- phase 1: ht[n][r] = x[r] . W1[n] + b1[n]   (4n x 4r register tile)
    const float4* w1v = (const float4*)W1;
    for (int it = 0; it < 4; it++) {
        int idx = it * 256 + tid;      // 0..1023
        int ng  = idx >> 3;            // 0..127  (node group of 4)
        int rq  = idx & 7;             // row group of 4
        float acc1[4][4];
        #pragma unroll
        for (int i = 0; i < 4; i++) {
            int n = ng * 4 + i;
            float bb = b1[n < 511 ? n : 510];
            #pragma unroll
            for (int j = 0; j < 4; j++) acc1[i][j] = bb;
        }
        #pragma unroll 4
        for (int k4 = 0; k4 < 32; k4++) {
            float4 w[4];
            #pragma unroll
            for (int i = 0; i < 4; i++) {
                int n = ng * 4 + i; if (n > 510) n = 510;
                w[i] = w1v[(size_t)n * 32 + k4];
            }
            float xv[4][4];
            #pragma unroll
            for (int kk = 0; kk < 4; kk++)
                #pragma unroll
                for (int j = 0; j < 4; j++)
                    xv[kk][j] = xs[(k4 * 4 + kk) * 33 + rq * 4 + j];
            #pragma unroll
            for (int i = 0; i < 4; i++)
                #pragma unroll
                for (int j = 0; j < 4; j++) {
                    acc1[i][j] = fmaf(w[i].x, xv[0][j], acc1[i][j]);
                    acc1[i][j] = fmaf(w[i].y, xv[1][j], acc1[i][j]);
                    acc1[i][j] = fmaf(w[i].z, xv[2][j], acc1[i][j]);
                    acc1[i][j] = fmaf(w[i].w, xv[3][j], acc1[i][j]);
                }
        }
        #pragma unroll
        for (int i = 0; i < 4; i++) {
            int n = ng * 4 + i;
            if (n < 511) {
                #pragma unroll
                for (int j = 0; j < 4; j++)
                    ht[n * TM + rq * 4 + j] = acc1[i][j];
            }
        }
    }
    if (tid < TM) ht[511 * TM + tid] = 0.0f;   // zero-pad node 511

    // ---- phase 2: y[r][l] = sum_j relu(h[r][j])*W2[l][j] + relu(-h[r][j])*W2[l][511+j]
    const int rg = tid >> 6;   // 0..3  -> rows rg*8..rg*8+7
    const int cg = tid & 63;   // 0..63 -> leaves cg*8..cg*8+7
    float acc[8][8];
    #pragma unroll
    for (int r = 0; r < 8; r++)
        #pragma unroll
        for (int c = 0; c < 8; c++) acc[r][c] = 0.0f;

    for (int j0 = 0; j0 < 512; j0 += KS) {
        __syncthreads();
        // stage W2 slice: j-fast mapping -> coalesced LDG, bank-skewed STS
        for (int i = tid; i < KS * 512; i += 256) {
            int l  = i >> 3;
            int jj = i & 7;
            int j  = j0 + jj;                         // 0..511 (j=511 is zero-padded node)
            int jb = 511 + (j < 511 ? j : 510);       // clamp avoids OOB; multiplied by 0
            ws[jj * WS_STRIDE + l]           = W2[(size_t)l * 1022 + j];
            ws[WS_HALF + jj * WS_STRIDE + l] = W2[(size_t)l * 1022 + jb];
        }
        __syncthreads();

        #pragma unroll
        for (int jj = 0; jj < KS; jj++) {
            int j = j0 + jj;
            const float4* ap = (const float4*)(ht + j * TM + rg * 8);
            float4 a0 = ap[0], a1 = ap[1];
            float p[8], m[8];
            p[0] = fmaxf(a0.x, 0.f); m[0] = fmaxf(-a0.x, 0.f);
            p[1] = fmaxf(a0.y, 0.f); m[1] = fmaxf(-a0.y, 0.f);
            p[2] = fmaxf(a0.z, 0.f); m[2] = fmaxf(-a0.z, 0.f);
            p[3] = fmaxf(a0.w, 0.f); m[3] = fmaxf(-a0.w, 0.f);
            p[4] = fmaxf(a1.x, 0.f); m[4] = fmaxf(-a1.x, 0.f);
            p[5] = fmaxf(a1.y, 0.f); m[5] = fmaxf(-a1.y, 0.f);
            p[6] = fmaxf(a1.z, 0.f); m[6] = fmaxf(-a1.z, 0.f);
            p[7] = fmaxf(a1.w, 0.f); m[7] = fmaxf(-a1.w, 0.f);

            const float4* bap = (const float4*)(ws + jj * WS_STRIDE + cg * 8);
            const float4* bbp = (const float4*)(ws + WS_HALF + jj * WS_STRIDE + cg * 8);
            float4 ba0 = bap[0], ba1 = bap[1];
            float4 bb0 = bbp[0], bb1 = bbp[1];
            float ba[8] = {ba0.x, ba0.y, ba0.z, ba0.w, ba1.x, ba1.y, ba1.z, ba1.w};
            float bb[8] = {bb0.x, bb0.y, bb0.z, bb0.w, bb1.x, bb1.y, bb1.z, bb1.w};

            #pragma unroll
            for (int r = 0; r < 8; r++)
                #pragma unroll
                for (int c = 0; c < 8; c++)
                    acc[r][c] = fmaf(p[r], ba[c], fmaf(m[r], bb[c], acc[r][c]));
        }
    }

    // ---- phase 3: grouped segment-max via shared atomicMax on ordered uints
    #pragma unroll
    for (int c = 0; c < 8; c++) {
        int l = cg * 8 + c;
        int a = leaf_actions[l] & 15;
        #pragma unroll
        for (int r = 0; r < 8; r++)
            atomicMax(&pool[(rg * 8 + r) * 16 + a], ford(acc[r][c]));
    }
    __syncthreads();

    // ---- softmax over 16 actions, one thread per row
    if (tid < TM) {
        float v[16];
        float mx = -3.402823466e38f;
        #pragma unroll
        for (int a = 0; a < 16; a++) {
            v[a] = funord(pool[tid * 16 + a]);
            mx = fmaxf(mx, v[a]);
        }
        float s = 0.f;
        #pragma unroll
        for (int a = 0; a < 16; a++) { v[a] = __expf(v[a] - mx); s += v[a]; }
        float inv = 1.f / s;
        float4* o = (float4*)(out + (size_t)(row0 + tid) * 16);
        o[0] = make_float4(v[0] * inv,  v[1] * inv,  v[2] * inv,  v[3] * inv);
        o[1] = make_float4(v[4] * inv,  v[5] * inv,  v[6] * inv,  v[7] * inv);
        o[2] = make_float4(v[8] * inv,  v[9] * inv,  v[10] * inv, v[11] * inv);
        o[3] = make_float4(v[12] * inv, v[13] * inv, v[14] * inv, v[15] * inv);
    }
}

extern "C" void kernel_launch(void* const* d_in, const int* in_sizes, int n_in,
                              void* d_out, int out_size)
{
    const float* x  = (const float*)d_in[0];
    const float* W1 = (const float*)d_in[1];
    const float* b1 = (const float*)d_in[2];
    const float* W2 = (const float*)d_in[3];
    const int*   la = (const int*)d_in[4];
    float* out = (float*)d_out;

    int Btot = in_sizes[0] / 128;          // 131072
    cudaFuncSetAttribute(dtnet_fused_kernel,
                         cudaFuncAttributeMaxDynamicSharedMemorySize, SMEM_BYTES);
    dtnet_fused_kernel<<<Btot / TM, 256, SMEM_BYTES>>>(x, W1, b1, W2, la, out);
}

// round 6
// speedup vs baseline: 4.0237x; 4.0237x over previous
#include <cuda_runtime.h>
#include <cuda_bf16.h>
#include <cstdint>

// B=131072, IN_DIM=128, N_NODES=511(pad 512), N_LEAVES=512, N_ACTIONS=16
#define XH_   0
#define XL_   32768
#define ZPH_  65536
#define ZPL_  81920
#define ZMH_  98304
#define ZML_  114688
#define ACT_  131072
#define POOL2_ 131584
#define SMEMB (131584 + 8192)

__device__ __align__(16) unsigned char g_w2f[2097152]; // 4096 frag-blocks x 512B
__device__ __align__(16) unsigned char g_w1f[262144];  // 512 frag-blocks x 512B
__device__ float g_b1p[512];

__device__ __forceinline__ uint32_t s2u(const void* p) {
    uint32_t a;
    asm("{ .reg .u64 t; cvta.to.shared.u64 t, %1; cvt.u32.u64 %0, t; }" : "=r"(a) : "l"(p));
    return a;
}
__device__ __forceinline__ void sp2(float a, float b, uint32_t& h, uint32_t& l) {
    __nv_bfloat16 ah = __float2bfloat16_rn(a), bh = __float2bfloat16_rn(b);
    __nv_bfloat16 al = __float2bfloat16_rn(a - __bfloat162float(ah));
    __nv_bfloat16 bl = __float2bfloat16_rn(b - __bfloat162float(bh));
    h = (uint32_t)*(uint16_t*)&ah | ((uint32_t)*(uint16_t*)&bh << 16);
    l = (uint32_t)*(uint16_t*)&al | ((uint32_t)*(uint16_t*)&bl << 16);
}
__device__ __forceinline__ void ldm4(uint32_t* r, uint32_t a) {
    asm volatile("ldmatrix.sync.aligned.m8n8.x4.shared.b16 {%0,%1,%2,%3}, [%4];"
                 : "=r"(r[0]), "=r"(r[1]), "=r"(r[2]), "=r"(r[3]) : "r"(a));
}
__device__ __forceinline__ void mma(float* d, const uint32_t* a, const uint32_t* b) {
    asm volatile(
        "mma.sync.aligned.m16n8k16.row.col.f32.bf16.bf16.f32 "
        "{%0,%1,%2,%3}, {%4,%5,%6,%7}, {%8,%9}, {%0,%1,%2,%3};"
        : "+f"(d[0]), "+f"(d[1]), "+f"(d[2]), "+f"(d[3])
        : "r"(a[0]), "r"(a[1]), "r"(a[2]), "r"(a[3]), "r"(b[0]), "r"(b[1]));
}
__device__ __forceinline__ unsigned ford(float f) {
    unsigned u = __float_as_uint(f);
    return (u & 0x80000000u) ? ~u : (u | 0x80000000u);
}
__device__ __forceinline__ float funord(unsigned s) {
    return __uint_as_float((s & 0x80000000u) ? (s ^ 0x80000000u) : ~s);
}

// ---- prep: bake fragment-major hi/lo bf16 weight images ----
__global__ void dtnet_prep(const float* __restrict__ W1, const float* __restrict__ b1,
                           const float* __restrict__ W2) {
    int idx = blockIdx.x * 256 + threadIdx.x;
    int lane = idx & 31, frag = idx >> 5;
    const int dd[4] = {0, 1, 8, 9};
    if (idx < 131072) {                       // W2 frags 0..4095: [s][kt][nt]
        int s = frag >> 9, kt = (frag >> 6) & 7, nt = frag & 63;
        int n = nt * 8 + (lane >> 2), k0 = kt * 16 + (lane & 3) * 2;
        float v[4];
        #pragma unroll
        for (int j = 0; j < 4; j++) {
            int kk = k0 + dd[j], g, c;
            if (kk < 64) { g = s * 64 + kk; c = g; }
            else         { g = s * 64 + kk - 64; c = 511 + g; }
            v[j] = (g < 511) ? W2[(size_t)n * 1022 + c] : 0.0f;
        }
        uint32_t h0, l0, h1, l1;
        sp2(v[0], v[1], h0, l0); sp2(v[2], v[3], h1, l1);
        *(uint4*)(g_w2f + (size_t)frag * 512 + lane * 16) = make_uint4(h0, h1, l0, l1);
    } else if (idx < 147456) {                // W1 frags 0..511: [s][kt][nt]
        int f2 = frag - 4096;
        int s = f2 >> 6, kt = (f2 >> 3) & 7, nt = f2 & 7;
        int g = s * 64 + nt * 8 + (lane >> 2), k0 = kt * 16 + (lane & 3) * 2;
        float v[4];
        #pragma unroll
        for (int j = 0; j < 4; j++)
            v[j] = (g < 511) ? W1[(size_t)g * 128 + k0 + dd[j]] : 0.0f;
        uint32_t h0, l0, h1, l1;
        sp2(v[0], v[1], h0, l0); sp2(v[2], v[3], h1, l1);
        *(uint4*)(g_w1f + (size_t)f2 * 512 + lane * 16) = make_uint4(h0, h1, l0, l1);
    }
    if (idx < 512) g_b1p[idx] = (idx < 511) ? b1[idx] : 0.0f;
}

// ---- main fused kernel: 128 rows/CTA, 2 leaf passes ----
__global__ __launch_bounds__(256, 1)
void dtnet_mma(const float* __restrict__ x, const int* __restrict__ la,
               float* __restrict__ out) {
    extern __shared__ unsigned char smc[];
    const uint32_t sb = s2u(smc);
    const int tid = threadIdx.x, w = tid >> 5, lane = tid & 31;
    const int row0 = blockIdx.x * 128;
    unsigned* pool = (unsigned*)(smc + POOL2_);
    const uint8_t* act = (const uint8_t*)(smc + ACT_);

    ((uint8_t*)(smc + ACT_))[tid] = (uint8_t)la[tid];
    ((uint8_t*)(smc + ACT_))[256 + tid] = (uint8_t)la[256 + tid];
    for (int i = tid; i < 2048; i += 256) pool[i] = 0u;

    // stage X [128 x 128] hi/lo bf16, swizzled 256B rows
    #pragma unroll
    for (int it = 0; it < 16; it++) {
        int idx = it * 256 + tid, r = idx >> 5, q = idx & 31;
        float4 v = ((const float4*)(x + (size_t)(row0 + r) * 128))[q];
        uint32_t h0, l0, h1, l1;
        sp2(v.x, v.y, h0, l0); sp2(v.z, v.w, h1, l1);
        int kb = q >> 1;
        uint32_t off = r * 256 + ((kb & 8) | ((kb ^ r) & 7)) * 16 + (q & 1) * 8;
        *(uint2*)(smc + XH_ + off) = make_uint2(h0, h1);
        *(uint2*)(smc + XL_ + off) = make_uint2(l0, l1);
    }
    __syncthreads();

    for (int pass = 0; pass < 2; pass++) {
        float acc[8][4][4];
        #pragma unroll
        for (int a = 0; a < 8; a++)
            #pragma unroll
            for (int b = 0; b < 4; b++)
                #pragma unroll
                for (int c = 0; c < 4; c++) acc[a][b][c] = 0.0f;

        for (int s = 0; s < 8; s++) {
            // ---- phase 1: h(16 rows/warp x 64 nodes) ----
            float hacc[8][4];
            #pragma unroll
            for (int a = 0; a < 8; a++)
                #pragma unroll
                for (int c = 0; c < 4; c++) hacc[a][c] = 0.0f;
            const int arow = w * 16 + (lane & 7) + ((lane >> 3) & 1) * 8;
            #pragma unroll
            for (int kt = 0; kt < 8; kt++) {
                int cc = kt * 2 + (lane >> 4);
                uint32_t ao = arow * 256 + ((cc & 8) | ((cc ^ arow) & 7)) * 16;
                uint32_t ah[4], al_[4];
                ldm4(ah, sb + XH_ + ao);
                ldm4(al_, sb + XL_ + ao);
                #pragma unroll
                for (int nt = 0; nt < 8; nt++) {
                    uint4 t = *(const uint4*)(g_w1f +
                        ((size_t)(((s * 8 + kt) * 8 + nt)) * 512 + lane * 16));
                    uint32_t bh[2] = {t.x, t.y}, bl[2] = {t.z, t.w};
                    mma(hacc[nt], ah, bh);
                    mma(hacc[nt], ah, bl);
                    mma(hacc[nt], al_, bh);
                }
            }
            // bias + relu(+/-) + split -> Z smem
            #pragma unroll
            for (int nt = 0; nt < 8; nt++) {
                int n0 = nt * 8 + (lane & 3) * 2, gn = s * 64 + n0;
                float bb0 = g_b1p[gn], bb1 = g_b1p[gn + 1];
                #pragma unroll
                for (int rh = 0; rh < 2; rh++) {
                    int row = w * 16 + (lane >> 2) + rh * 8;
                    float h0 = hacc[nt][rh * 2] + bb0, h1 = hacc[nt][rh * 2 + 1] + bb1;
                    uint32_t ph, pl, mh, ml;
                    sp2(fmaxf(h0, 0.f), fmaxf(h1, 0.f), ph, pl);
                    sp2(fmaxf(-h0, 0.f), fmaxf(-h1, 0.f), mh, ml);
                    uint32_t off = row * 128 + (((nt ^ row) & 7) * 16) + (lane & 3) * 4;
                    *(uint32_t*)(smc + ZPH_ + off) = ph;
                    *(uint32_t*)(smc + ZPL_ + off) = pl;
                    *(uint32_t*)(smc + ZMH_ + off) = mh;
                    *(uint32_t*)(smc + ZML_ + off) = ml;
                }
            }
            __syncthreads();
            // ---- phase 2: acc += Z . W2slab^T (128 rows x 32 leaves/warp) ----
            #pragma unroll
            for (int kt = 0; kt < 8; kt++) {
                uint32_t zh = (kt < 4) ? ZPH_ : ZMH_;
                uint32_t zl = zh + 16384;
                int ktl = kt & 3;
                uint4 tb[4];
                #pragma unroll
                for (int ntl = 0; ntl < 4; ntl++)
                    tb[ntl] = *(const uint4*)(g_w2f +
                        ((size_t)((s * 8 + kt) * 64 + pass * 32 + w * 4 + ntl) * 512
                         + lane * 16));
                int cc = ktl * 2 + (lane >> 4);
                #pragma unroll
                for (int mt = 0; mt < 8; mt++) {
                    int row = mt * 16 + (lane & 7) + ((lane >> 3) & 1) * 8;
                    uint32_t ao = row * 128 + (((cc ^ row) & 7) * 16);
                    uint32_t ah[4], al_[4];
                    ldm4(ah, sb + zh + ao);
                    ldm4(al_, sb + zl + ao);
                    #pragma unroll
                    for (int ntl = 0; ntl < 4; ntl++) {
                        uint32_t bh[2] = {tb[ntl].x, tb[ntl].y};
                        uint32_t bl[2] = {tb[ntl].z, tb[ntl].w};
                        mma(acc[mt][ntl], ah, bh);
                        mma(acc[mt][ntl], ah, bl);
                        mma(acc[mt][ntl], al_, bh);
                    }
                }
            }
            __syncthreads();
        }
        // ---- per-pass epilogue: segment-max into persistent pool ----
        #pragma unroll
        for (int mt = 0; mt < 8; mt++)
            #pragma unroll
            for (int ntl = 0; ntl < 4; ntl++)
                #pragma unroll
                for (int i = 0; i < 2; i++) {
                    int col = pass * 256 + w * 32 + ntl * 8 + (lane & 3) * 2 + i;
                    int a = act[col];
                    #pragma unroll
                    for (int rh = 0; rh < 2; rh++) {
                        int row = mt * 16 + (lane >> 2) + rh * 8;
                        atomicMax(&pool[row * 16 + a], ford(acc[mt][ntl][rh * 2 + i]));
                    }
                }
        __syncthreads();
    }

    // ---- softmax ----
    if (tid < 128) {
        float v[16], mx = -3.402823466e38f;
        #pragma unroll
        for (int a = 0; a < 16; a++) {
            v[a] = funord(pool[tid * 16 + a]);
            mx = fmaxf(mx, v[a]);
        }
        float sum = 0.f;
        #pragma unroll
        for (int a = 0; a < 16; a++) { v[a] = __expf(v[a] - mx); sum += v[a]; }
        float inv = 1.f / sum;
        float4* o = (float4*)(out + (size_t)(row0 + tid) * 16);
        o[0] = make_float4(v[0] * inv, v[1] * inv, v[2] * inv, v[3] * inv);
        o[1] = make_float4(v[4] * inv, v[5] * inv, v[6] * inv, v[7] * inv);
        o[2] = make_float4(v[8] * inv, v[9] * inv, v[10] * inv, v[11] * inv);
        o[3] = make_float4(v[12] * inv, v[13] * inv, v[14] * inv, v[15] * inv);
    }
}

extern "C" void kernel_launch(void* const* d_in, const int* in_sizes, int n_in,
                              void* d_out, int out_size) {
    const float* x  = (const float*)d_in[0];
    const float* W1 = (const float*)d_in[1];
    const float* b1 = (const float*)d_in[2];
    const float* W2 = (const float*)d_in[3];
    const int*   la = (const int*)d_in[4];
    float* out = (float*)d_out;

    dtnet_prep<<<576, 256>>>(W1, b1, W2);
    cudaFuncSetAttribute(dtnet_mma, cudaFuncAttributeMaxDynamicSharedMemorySize, SMEMB);
    int Btot = in_sizes[0] / 128;   // 131072
    dtnet_mma<<<Btot / 128, 256, SMEMB>>>(x, la, out);
}

// round 7
// speedup vs baseline: 4.5578x; 1.1327x over previous
#include <cuda_runtime.h>
#include <cuda_bf16.h>
#include <cstdint>

// B=131072, IN_DIM=128, N_NODES=511(pad 512), N_LEAVES=512, N_ACTIONS=16
// 64 rows/CTA, all 512 leaves in one pass (128 acc regs/thread)
#define XH_   0
#define XL_   16384
#define ZPH_  32768
#define ZPL_  40960
#define ZMH_  49152
#define ZML_  57344
#define ACT_  65536
#define POOL_ 66048
#define SMEMB (66048 + 4096)

__device__ __align__(16) unsigned char g_w2f[2097152]; // 4096 frag-blocks x 512B
__device__ __align__(16) unsigned char g_w1f[262144];  // 512 frag-blocks x 512B
__device__ float g_b1p[512];

__device__ __forceinline__ uint32_t s2u(const void* p) {
    uint32_t a;
    asm("{ .reg .u64 t; cvta.to.shared.u64 t, %1; cvt.u32.u64 %0, t; }" : "=r"(a) : "l"(p));
    return a;
}
__device__ __forceinline__ void sp2(float a, float b, uint32_t& h, uint32_t& l) {
    __nv_bfloat16 ah = __float2bfloat16_rn(a), bh = __float2bfloat16_rn(b);
    __nv_bfloat16 al = __float2bfloat16_rn(a - __bfloat162float(ah));
    __nv_bfloat16 bl = __float2bfloat16_rn(b - __bfloat162float(bh));
    h = (uint32_t)*(uint16_t*)&ah | ((uint32_t)*(uint16_t*)&bh << 16);
    l = (uint32_t)*(uint16_t*)&al | ((uint32_t)*(uint16_t*)&bl << 16);
}
__device__ __forceinline__ void ldm4(uint32_t* r, uint32_t a) {
    asm volatile("ldmatrix.sync.aligned.m8n8.x4.shared.b16 {%0,%1,%2,%3}, [%4];"
                 : "=r"(r[0]), "=r"(r[1]), "=r"(r[2]), "=r"(r[3]) : "r"(a));
}
__device__ __forceinline__ void mma(float* d, const uint32_t* a, const uint32_t* b) {
    asm volatile(
        "mma.sync.aligned.m16n8k16.row.col.f32.bf16.bf16.f32 "
        "{%0,%1,%2,%3}, {%4,%5,%6,%7}, {%8,%9}, {%0,%1,%2,%3};"
        : "+f"(d[0]), "+f"(d[1]), "+f"(d[2]), "+f"(d[3])
        : "r"(a[0]), "r"(a[1]), "r"(a[2]), "r"(a[3]), "r"(b[0]), "r"(b[1]));
}
__device__ __forceinline__ unsigned ford(float f) {
    unsigned u = __float_as_uint(f);
    return (u & 0x80000000u) ? ~u : (u | 0x80000000u);
}
__device__ __forceinline__ float funord(unsigned s) {
    return __uint_as_float((s & 0x80000000u) ? (s ^ 0x80000000u) : ~s);
}

// ---- prep: bake fragment-major hi/lo bf16 weight images (unchanged layouts) ----
__global__ void dtnet_prep(const float* __restrict__ W1, const float* __restrict__ b1,
                           const float* __restrict__ W2) {
    int idx = blockIdx.x * 256 + threadIdx.x;
    int lane = idx & 31, frag = idx >> 5;
    const int dd[4] = {0, 1, 8, 9};
    if (idx < 131072) {                       // W2 frags 0..4095: [s][kt][nt]
        int s = frag >> 9, kt = (frag >> 6) & 7, nt = frag & 63;
        int n = nt * 8 + (lane >> 2), k0 = kt * 16 + (lane & 3) * 2;
        float v[4];
        #pragma unroll
        for (int j = 0; j < 4; j++) {
            int kk = k0 + dd[j], g, c;
            if (kk < 64) { g = s * 64 + kk; c = g; }
            else         { g = s * 64 + kk - 64; c = 511 + g; }
            v[j] = (g < 511) ? W2[(size_t)n * 1022 + c] : 0.0f;
        }
        uint32_t h0, l0, h1, l1;
        sp2(v[0], v[1], h0, l0); sp2(v[2], v[3], h1, l1);
        *(uint4*)(g_w2f + (size_t)frag * 512 + lane * 16) = make_uint4(h0, h1, l0, l1);
    } else if (idx < 147456) {                // W1 frags 0..511: [s][kt][nt]
        int f2 = frag - 4096;
        int s = f2 >> 6, kt = (f2 >> 3) & 7, nt = f2 & 7;
        int g = s * 64 + nt * 8 + (lane >> 2), k0 = kt * 16 + (lane & 3) * 2;
        float v[4];
        #pragma unroll
        for (int j = 0; j < 4; j++)
            v[j] = (g < 511) ? W1[(size_t)g * 128 + k0 + dd[j]] : 0.0f;
        uint32_t h0, l0, h1, l1;
        sp2(v[0], v[1], h0, l0); sp2(v[2], v[3], h1, l1);
        *(uint4*)(g_w1f + (size_t)f2 * 512 + lane * 16) = make_uint4(h0, h1, l0, l1);
    }
    if (idx < 512) g_b1p[idx] = (idx < 511) ? b1[idx] : 0.0f;
}

// ---- main fused kernel: 64 rows/CTA, single leaf pass ----
__global__ __launch_bounds__(256, 1)
void dtnet_mma(const float* __restrict__ x, const int* __restrict__ la,
               float* __restrict__ out) {
    extern __shared__ unsigned char smc[];
    const uint32_t sb = s2u(smc);
    const int tid = threadIdx.x, w = tid >> 5, lane = tid & 31;
    const int row0 = blockIdx.x * 64;
    unsigned* pool = (unsigned*)(smc + POOL_);
    const uint8_t* act = (const uint8_t*)(smc + ACT_);

    ((uint8_t*)(smc + ACT_))[tid] = (uint8_t)la[tid];
    ((uint8_t*)(smc + ACT_))[256 + tid] = (uint8_t)la[256 + tid];
    for (int i = tid; i < 1024; i += 256) pool[i] = 0u;

    // stage X [64 x 128] hi/lo bf16, swizzled 256B rows
    #pragma unroll
    for (int it = 0; it < 8; it++) {
        int idx = it * 256 + tid, r = idx >> 5, q = idx & 31;
        float4 v = ((const float4*)(x + (size_t)(row0 + r) * 128))[q];
        uint32_t h0, l0, h1, l1;
        sp2(v.x, v.y, h0, l0); sp2(v.z, v.w, h1, l1);
        int kb = q >> 1;
        uint32_t off = r * 256 + ((kb & 8) | ((kb ^ r) & 7)) * 16 + (q & 1) * 8;
        *(uint2*)(smc + XH_ + off) = make_uint2(h0, h1);
        *(uint2*)(smc + XL_ + off) = make_uint2(l0, l1);
    }
    __syncthreads();

    float acc[4][8][4];
    #pragma unroll
    for (int a = 0; a < 4; a++)
        #pragma unroll
        for (int b = 0; b < 8; b++)
            #pragma unroll
            for (int c = 0; c < 4; c++) acc[a][b][c] = 0.0f;

    for (int s = 0; s < 8; s++) {
        // ---- phase 1: H(64 x 64). warp = (w&3) row-tile x (w>>2) node-half ----
        float hacc[4][4];
        #pragma unroll
        for (int a = 0; a < 4; a++)
            #pragma unroll
            for (int c = 0; c < 4; c++) hacc[a][c] = 0.0f;
        const int arow = (w & 3) * 16 + (lane & 7) + ((lane >> 3) & 1) * 8;
        #pragma unroll
        for (int kt = 0; kt < 8; kt++) {
            int cc = kt * 2 + (lane >> 4);
            uint32_t ao = arow * 256 + ((cc & 8) | ((cc ^ arow) & 7)) * 16;
            uint32_t ah[4], al_[4];
            ldm4(ah, sb + XH_ + ao);
            ldm4(al_, sb + XL_ + ao);
            #pragma unroll
            for (int ntl = 0; ntl < 4; ntl++) {
                int nt = (w >> 2) * 4 + ntl;
                uint4 t = *(const uint4*)(g_w1f +
                    ((size_t)((s * 8 + kt) * 8 + nt) * 512 + lane * 16));
                uint32_t bh[2] = {t.x, t.y}, bl[2] = {t.z, t.w};
                mma(hacc[ntl], ah, bh);
                mma(hacc[ntl], ah, bl);
                mma(hacc[ntl], al_, bh);
            }
        }
        // bias + relu(+/-) + split -> Z smem
        #pragma unroll
        for (int ntl = 0; ntl < 4; ntl++) {
            int nt = (w >> 2) * 4 + ntl;
            int nloc = nt * 8 + (lane & 3) * 2, gn = s * 64 + nloc;
            float bb0 = g_b1p[gn], bb1 = g_b1p[gn + 1];
            #pragma unroll
            for (int rh = 0; rh < 2; rh++) {
                int row = (w & 3) * 16 + (lane >> 2) + rh * 8;
                float h0 = hacc[ntl][rh * 2] + bb0, h1 = hacc[ntl][rh * 2 + 1] + bb1;
                uint32_t ph, pl, mh, ml;
                sp2(fmaxf(h0, 0.f), fmaxf(h1, 0.f), ph, pl);
                sp2(fmaxf(-h0, 0.f), fmaxf(-h1, 0.f), mh, ml);
                uint32_t off = row * 128 + (((nt ^ row) & 7) * 16) + (lane & 3) * 4;
                *(uint32_t*)(smc + ZPH_ + off) = ph;
                *(uint32_t*)(smc + ZPL_ + off) = pl;
                *(uint32_t*)(smc + ZMH_ + off) = mh;
                *(uint32_t*)(smc + ZML_ + off) = ml;
            }
        }
        __syncthreads();
        // ---- phase 2: acc += Z . W2slab^T (64 rows x 64 leaves/warp) ----
        #pragma unroll
        for (int kt = 0; kt < 8; kt++) {
            uint32_t zh = (kt < 4) ? ZPH_ : ZMH_;
            uint32_t zl = zh + 8192;
            int ktl = kt & 3;
            uint4 tb[8];
            #pragma unroll
            for (int ntl = 0; ntl < 8; ntl++)
                tb[ntl] = *(const uint4*)(g_w2f +
                    ((size_t)((s * 8 + kt) * 64 + w * 8 + ntl) * 512 + lane * 16));
            int cc = ktl * 2 + (lane >> 4);
            #pragma unroll
            for (int mt = 0; mt < 4; mt++) {
                int row = mt * 16 + (lane & 7) + ((lane >> 3) & 1) * 8;
                uint32_t ao = row * 128 + (((cc ^ row) & 7) * 16);
                uint32_t ah[4], al_[4];
                ldm4(ah, sb + zh + ao);
                ldm4(al_, sb + zl + ao);
                #pragma unroll
                for (int ntl = 0; ntl < 8; ntl++) {
                    uint32_t bh[2] = {tb[ntl].x, tb[ntl].y};
                    uint32_t bl[2] = {tb[ntl].z, tb[ntl].w};
                    mma(acc[mt][ntl], ah, bh);
                    mma(acc[mt][ntl], ah, bl);
                    mma(acc[mt][ntl], al_, bh);
                }
            }
        }
        __syncthreads();
    }

    // ---- epilogue: segment-max + softmax ----
    #pragma unroll
    for (int mt = 0; mt < 4; mt++)
        #pragma unroll
        for (int ntl = 0; ntl < 8; ntl++)
            #pragma unroll
            for (int i = 0; i < 2; i++) {
                int col = w * 64 + ntl * 8 + (lane & 3) * 2 + i;
                int a = act[col];
                #pragma unroll
                for (int rh = 0; rh < 2; rh++) {
                    int row = mt * 16 + (lane >> 2) + rh * 8;
                    atomicMax(&pool[row * 16 + a], ford(acc[mt][ntl][rh * 2 + i]));
                }
            }
    __syncthreads();
    if (tid < 64) {
        float v[16], mx = -3.402823466e38f;
        #pragma unroll
        for (int a = 0; a < 16; a++) {
            v[a] = funord(pool[tid * 16 + a]);
            mx = fmaxf(mx, v[a]);
        }
        float sum = 0.f;
        #pragma unroll
        for (int a = 0; a < 16; a++) { v[a] = __expf(v[a] - mx); sum += v[a]; }
        float inv = 1.f / sum;
        float4* o = (float4*)(out + (size_t)(row0 + tid) * 16);
        o[0] = make_float4(v[0] * inv, v[1] * inv, v[2] * inv, v[3] * inv);
        o[1] = make_float4(v[4] * inv, v[5] * inv, v[6] * inv, v[7] * inv);
        o[2] = make_float4(v[8] * inv, v[9] * inv, v[10] * inv, v[11] * inv);
        o[3] = make_float4(v[12] * inv, v[13] * inv, v[14] * inv, v[15] * inv);
    }
}

extern "C" void kernel_launch(void* const* d_in, const int* in_sizes, int n_in,
                              void* d_out, int out_size) {
    const float* x  = (const float*)d_in[0];
    const float* W1 = (const float*)d_in[1];
    const float* b1 = (const float*)d_in[2];
    const float* W2 = (const float*)d_in[3];
    const int*   la = (const int*)d_in[4];
    float* out = (float*)d_out;

    dtnet_prep<<<576, 256>>>(W1, b1, W2);
    cudaFuncSetAttribute(dtnet_mma, cudaFuncAttributeMaxDynamicSharedMemorySize, SMEMB);
    int Btot = in_sizes[0] / 128;   // 131072
    dtnet_mma<<<Btot / 64, 256, SMEMB>>>(x, la, out);
}

// round 8
// speedup vs baseline: 4.8541x; 1.0650x over previous
#include <cuda_runtime.h>
#include <cuda_bf16.h>
#include <cstdint>

// B=131072, IN_DIM=128, N_NODES=511(pad 512), N_LEAVES=512, N_ACTIONS=16
// 64 rows/CTA, all 512 leaves in one pass, Z double-buffered (1 sync/slab)
#define XH_   0
#define XL_   16384
#define Z0_   32768          // buf0: ZPH/ZPL/ZMH/ZML 8KB each
#define Z1_   65536          // buf1
#define ACT_  98304
#define POOL_ 98816
#define SMEMB (98816 + 4096)

__device__ __align__(16) unsigned char g_w2f[2097152]; // 4096 frag-blocks x 512B
__device__ __align__(16) unsigned char g_w1f[262144];  // 512 frag-blocks x 512B
__device__ float g_b1p[512];

__device__ __forceinline__ uint32_t s2u(const void* p) {
    uint32_t a;
    asm("{ .reg .u64 t; cvta.to.shared.u64 t, %1; cvt.u32.u64 %0, t; }" : "=r"(a) : "l"(p));
    return a;
}
__device__ __forceinline__ void sp2(float a, float b, uint32_t& h, uint32_t& l) {
    __nv_bfloat16 ah = __float2bfloat16_rn(a), bh = __float2bfloat16_rn(b);
    __nv_bfloat16 al = __float2bfloat16_rn(a - __bfloat162float(ah));
    __nv_bfloat16 bl = __float2bfloat16_rn(b - __bfloat162float(bh));
    h = (uint32_t)*(uint16_t*)&ah | ((uint32_t)*(uint16_t*)&bh << 16);
    l = (uint32_t)*(uint16_t*)&al | ((uint32_t)*(uint16_t*)&bl << 16);
}
__device__ __forceinline__ void ldm4(uint32_t* r, uint32_t a) {
    asm volatile("ldmatrix.sync.aligned.m8n8.x4.shared.b16 {%0,%1,%2,%3}, [%4];"
                 : "=r"(r[0]), "=r"(r[1]), "=r"(r[2]), "=r"(r[3]) : "r"(a));
}
__device__ __forceinline__ void mma(float* d, const uint32_t* a, const uint32_t* b) {
    asm volatile(
        "mma.sync.aligned.m16n8k16.row.col.f32.bf16.bf16.f32 "
        "{%0,%1,%2,%3}, {%4,%5,%6,%7}, {%8,%9}, {%0,%1,%2,%3};"
        : "+f"(d[0]), "+f"(d[1]), "+f"(d[2]), "+f"(d[3])
        : "r"(a[0]), "r"(a[1]), "r"(a[2]), "r"(a[3]), "r"(b[0]), "r"(b[1]));
}
__device__ __forceinline__ unsigned ford(float f) {
    unsigned u = __float_as_uint(f);
    return (u & 0x80000000u) ? ~u : (u | 0x80000000u);
}
__device__ __forceinline__ float funord(unsigned s) {
    return __uint_as_float((s & 0x80000000u) ? (s ^ 0x80000000u) : ~s);
}

// ---- prep: bake fragment-major hi/lo bf16 weight images (unchanged) ----
__global__ void dtnet_prep(const float* __restrict__ W1, const float* __restrict__ b1,
                           const float* __restrict__ W2) {
    int idx = blockIdx.x * 256 + threadIdx.x;
    int lane = idx & 31, frag = idx >> 5;
    const int dd[4] = {0, 1, 8, 9};
    if (idx < 131072) {                       // W2 frags 0..4095: [s][kt][nt]
        int s = frag >> 9, kt = (frag >> 6) & 7, nt = frag & 63;
        int n = nt * 8 + (lane >> 2), k0 = kt * 16 + (lane & 3) * 2;
        float v[4];
        #pragma unroll
        for (int j = 0; j < 4; j++) {
            int kk = k0 + dd[j], g, c;
            if (kk < 64) { g = s * 64 + kk; c = g; }
            else         { g = s * 64 + kk - 64; c = 511 + g; }
            v[j] = (g < 511) ? W2[(size_t)n * 1022 + c] : 0.0f;
        }
        uint32_t h0, l0, h1, l1;
        sp2(v[0], v[1], h0, l0); sp2(v[2], v[3], h1, l1);
        *(uint4*)(g_w2f + (size_t)frag * 512 + lane * 16) = make_uint4(h0, h1, l0, l1);
    } else if (idx < 147456) {                // W1 frags 0..511: [s][kt][nt]
        int f2 = frag - 4096;
        int s = f2 >> 6, kt = (f2 >> 3) & 7, nt = f2 & 7;
        int g = s * 64 + nt * 8 + (lane >> 2), k0 = kt * 16 + (lane & 3) * 2;
        float v[4];
        #pragma unroll
        for (int j = 0; j < 4; j++)
            v[j] = (g < 511) ? W1[(size_t)g * 128 + k0 + dd[j]] : 0.0f;
        uint32_t h0, l0, h1, l1;
        sp2(v[0], v[1], h0, l0); sp2(v[2], v[3], h1, l1);
        *(uint4*)(g_w1f + (size_t)f2 * 512 + lane * 16) = make_uint4(h0, h1, l0, l1);
    }
    if (idx < 512) g_b1p[idx] = (idx < 511) ? b1[idx] : 0.0f;
}

// ---- main fused kernel ----
__global__ __launch_bounds__(256, 1)
void dtnet_mma(const float* __restrict__ x, const int* __restrict__ la,
               float* __restrict__ out) {
    extern __shared__ unsigned char smc[];
    const uint32_t sb = s2u(smc);
    const int tid = threadIdx.x, w = tid >> 5, lane = tid & 31;
    const int row0 = blockIdx.x * 64;
    unsigned* pool = (unsigned*)(smc + POOL_);
    const uint8_t* act = (const uint8_t*)(smc + ACT_);

    ((uint8_t*)(smc + ACT_))[tid] = (uint8_t)la[tid];
    ((uint8_t*)(smc + ACT_))[256 + tid] = (uint8_t)la[256 + tid];
    for (int i = tid; i < 1024; i += 256) pool[i] = 0u;

    // stage X [64 x 128] hi/lo bf16, swizzled 256B rows
    #pragma unroll
    for (int it = 0; it < 8; it++) {
        int idx = it * 256 + tid, r = idx >> 5, q = idx & 31;
        float4 v = ((const float4*)(x + (size_t)(row0 + r) * 128))[q];
        uint32_t h0, l0, h1, l1;
        sp2(v.x, v.y, h0, l0); sp2(v.z, v.w, h1, l1);
        int kb = q >> 1;
        uint32_t off = r * 256 + ((kb & 8) | ((kb ^ r) & 7)) * 16 + (q & 1) * 8;
        *(uint2*)(smc + XH_ + off) = make_uint2(h0, h1);
        *(uint2*)(smc + XL_ + off) = make_uint2(l0, l1);
    }
    __syncthreads();

    float acc[4][8][4];
    #pragma unroll
    for (int a = 0; a < 4; a++)
        #pragma unroll
        for (int b = 0; b < 8; b++)
            #pragma unroll
            for (int c = 0; c < 4; c++) acc[a][b][c] = 0.0f;

    for (int s = 0; s < 8; s++) {
        const uint32_t zbase = (s & 1) ? Z1_ : Z0_;
        // ---- phase 1: H(64 x 64) ----
        float hacc[4][4];
        #pragma unroll
        for (int a = 0; a < 4; a++)
            #pragma unroll
            for (int c = 0; c < 4; c++) hacc[a][c] = 0.0f;
        const int arow = (w & 3) * 16 + (lane & 7) + ((lane >> 3) & 1) * 8;
        #pragma unroll
        for (int kt = 0; kt < 8; kt++) {
            int cc = kt * 2 + (lane >> 4);
            uint32_t ao = arow * 256 + ((cc & 8) | ((cc ^ arow) & 7)) * 16;
            uint32_t ah[4], al_[4];
            ldm4(ah, sb + XH_ + ao);
            ldm4(al_, sb + XL_ + ao);
            uint4 t1[4];
            #pragma unroll
            for (int ntl = 0; ntl < 4; ntl++)
                t1[ntl] = *(const uint4*)(g_w1f +
                    ((size_t)((s * 8 + kt) * 8 + (w >> 2) * 4 + ntl) * 512 + lane * 16));
            #pragma unroll
            for (int ntl = 0; ntl < 4; ntl++) {
                uint32_t bh[2] = {t1[ntl].x, t1[ntl].y};
                mma(hacc[ntl], ah, bh);
            }
            #pragma unroll
            for (int ntl = 0; ntl < 4; ntl++) {
                uint32_t bl[2] = {t1[ntl].z, t1[ntl].w};
                mma(hacc[ntl], ah, bl);
            }
            #pragma unroll
            for (int ntl = 0; ntl < 4; ntl++) {
                uint32_t bh[2] = {t1[ntl].x, t1[ntl].y};
                mma(hacc[ntl], al_, bh);
            }
        }
        // bias + relu(+/-) + split -> Z smem (current buffer)
        #pragma unroll
        for (int ntl = 0; ntl < 4; ntl++) {
            int nt = (w >> 2) * 4 + ntl;
            int nloc = nt * 8 + (lane & 3) * 2, gn = s * 64 + nloc;
            float bb0 = g_b1p[gn], bb1 = g_b1p[gn + 1];
            #pragma unroll
            for (int rh = 0; rh < 2; rh++) {
                int row = (w & 3) * 16 + (lane >> 2) + rh * 8;
                float h0 = hacc[ntl][rh * 2] + bb0, h1 = hacc[ntl][rh * 2 + 1] + bb1;
                uint32_t ph, pl, mh, ml;
                sp2(fmaxf(h0, 0.f), fmaxf(h1, 0.f), ph, pl);
                sp2(fmaxf(-h0, 0.f), fmaxf(-h1, 0.f), mh, ml);
                uint32_t off = row * 128 + (((nt ^ row) & 7) * 16) + (lane & 3) * 4;
                *(uint32_t*)(smc + zbase + off) = ph;           // ZPH
                *(uint32_t*)(smc + zbase + 8192 + off) = pl;    // ZPL
                *(uint32_t*)(smc + zbase + 16384 + off) = mh;   // ZMH
                *(uint32_t*)(smc + zbase + 24576 + off) = ml;   // ZML
            }
        }
        __syncthreads();   // single barrier per slab
        // ---- phase 2: acc += Z . W2slab^T (64 rows x 64 leaves/warp) ----
        #pragma unroll
        for (int kt = 0; kt < 8; kt++) {
            uint32_t zh = zbase + ((kt < 4) ? 0 : 16384);
            uint32_t zl = zh + 8192;
            int ktl = kt & 3;
            uint4 tb[8];
            #pragma unroll
            for (int ntl = 0; ntl < 8; ntl++)
                tb[ntl] = *(const uint4*)(g_w2f +
                    ((size_t)((s * 8 + kt) * 64 + w * 8 + ntl) * 512 + lane * 16));
            int cc = ktl * 2 + (lane >> 4);
            #pragma unroll
            for (int mt = 0; mt < 4; mt++) {
                int row = mt * 16 + (lane & 7) + ((lane >> 3) & 1) * 8;
                uint32_t ao = row * 128 + (((cc ^ row) & 7) * 16);
                uint32_t ah[4], al_[4];
                ldm4(ah, sb + zh + ao);
                ldm4(al_, sb + zl + ao);
                #pragma unroll
                for (int ntl = 0; ntl < 8; ntl++) {
                    uint32_t bh[2] = {tb[ntl].x, tb[ntl].y};
                    mma(acc[mt][ntl], ah, bh);
                }
                #pragma unroll
                for (int ntl = 0; ntl < 8; ntl++) {
                    uint32_t bl[2] = {tb[ntl].z, tb[ntl].w};
                    mma(acc[mt][ntl], ah, bl);
                }
                #pragma unroll
                for (int ntl = 0; ntl < 8; ntl++) {
                    uint32_t bh[2] = {tb[ntl].x, tb[ntl].y};
                    mma(acc[mt][ntl], al_, bh);
                }
            }
        }
        // no trailing sync: next slab writes the other Z buffer
    }

    // ---- epilogue: segment-max + softmax ----
    #pragma unroll
    for (int mt = 0; mt < 4; mt++)
        #pragma unroll
        for (int ntl = 0; ntl < 8; ntl++)
            #pragma unroll
            for (int i = 0; i < 2; i++) {
                int col = w * 64 + ntl * 8 + (lane & 3) * 2 + i;
                int a = act[col];
                #pragma unroll
                for (int rh = 0; rh < 2; rh++) {
                    int row = mt * 16 + (lane >> 2) + rh * 8;
                    atomicMax(&pool[row * 16 + a], ford(acc[mt][ntl][rh * 2 + i]));
                }
            }
    __syncthreads();
    if (tid < 64) {
        float v[16], mx = -3.402823466e38f;
        #pragma unroll
        for (int a = 0; a < 16; a++) {
            v[a] = funord(pool[tid * 16 + a]);
            mx = fmaxf(mx, v[a]);
        }
        float sum = 0.f;
        #pragma unroll
        for (int a = 0; a < 16; a++) { v[a] = __expf(v[a] - mx); sum += v[a]; }
        float inv = 1.f / sum;
        float4* o = (float4*)(out + (size_t)(row0 + tid) * 16);
        o[0] = make_float4(v[0] * inv, v[1] * inv, v[2] * inv, v[3] * inv);
        o[1] = make_float4(v[4] * inv, v[5] * inv, v[6] * inv, v[7] * inv);
        o[2] = make_float4(v[8] * inv, v[9] * inv, v[10] * inv, v[11] * inv);
        o[3] = make_float4(v[12] * inv, v[13] * inv, v[14] * inv, v[15] * inv);
    }
}

extern "C" void kernel_launch(void* const* d_in, const int* in_sizes, int n_in,
                              void* d_out, int out_size) {
    const float* x  = (const float*)d_in[0];
    const float* W1 = (const float*)d_in[1];
    const float* b1 = (const float*)d_in[2];
    const float* W2 = (const float*)d_in[3];
    const int*   la = (const int*)d_in[4];
    float* out = (float*)d_out;

    dtnet_prep<<<576, 256>>>(W1, b1, W2);
    cudaFuncSetAttribute(dtnet_mma, cudaFuncAttributeMaxDynamicSharedMemorySize, SMEMB);
    int Btot = in_sizes[0] / 128;   // 131072
    dtnet_mma<<<Btot / 64, 256, SMEMB>>>(x, la, out);
}

// round 9
// speedup vs baseline: 6.4737x; 1.3337x over previous
#include <cuda_runtime.h>
#include <cuda_fp16.h>
#include <cstdint>

// B=131072, IN_DIM=128, N_NODES=511(pad 512), N_LEAVES=512, N_ACTIONS=16
// 64 rows/CTA, fp16 2-term: A(X,Z)=fp16 hi, B(W1,W2)=fp16 hi+lo
#define XH_   0
#define Z0_   16384          // zph 8KB @+0, zmh 8KB @+8192
#define Z1_   32768
#define ACT_  49152
#define POOL_ 49664
#define SMEMB (49664 + 4096)

__device__ __align__(16) unsigned char g_w2f[2097152]; // 4096 frag-blocks x 512B
__device__ __align__(16) unsigned char g_w1f[262144];  // 512 frag-blocks x 512B
__device__ float g_b1p[512];

__device__ __forceinline__ uint32_t s2u(const void* p) {
    uint32_t a;
    asm("{ .reg .u64 t; cvta.to.shared.u64 t, %1; cvt.u32.u64 %0, t; }" : "=r"(a) : "l"(p));
    return a;
}
__device__ __forceinline__ uint32_t pk2(float a, float b) {   // fp16 hi pack
    __half ah = __float2half_rn(a), bh = __float2half_rn(b);
    return (uint32_t)*(uint16_t*)&ah | ((uint32_t)*(uint16_t*)&bh << 16);
}
__device__ __forceinline__ void sp2f(float a, float b, uint32_t& h, uint32_t& l) {
    __half ah = __float2half_rn(a), bh = __float2half_rn(b);
    __half al = __float2half_rn(a - __half2float(ah));
    __half bl = __float2half_rn(b - __half2float(bh));
    h = (uint32_t)*(uint16_t*)&ah | ((uint32_t)*(uint16_t*)&bh << 16);
    l = (uint32_t)*(uint16_t*)&al | ((uint32_t)*(uint16_t*)&bl << 16);
}
__device__ __forceinline__ void ldm4(uint32_t* r, uint32_t a) {
    asm volatile("ldmatrix.sync.aligned.m8n8.x4.shared.b16 {%0,%1,%2,%3}, [%4];"
                 : "=r"(r[0]), "=r"(r[1]), "=r"(r[2]), "=r"(r[3]) : "r"(a));
}
__device__ __forceinline__ void mma(float* d, const uint32_t* a, const uint32_t* b) {
    asm volatile(
        "mma.sync.aligned.m16n8k16.row.col.f32.f16.f16.f32 "
        "{%0,%1,%2,%3}, {%4,%5,%6,%7}, {%8,%9}, {%0,%1,%2,%3};"
        : "+f"(d[0]), "+f"(d[1]), "+f"(d[2]), "+f"(d[3])
        : "r"(a[0]), "r"(a[1]), "r"(a[2]), "r"(a[3]), "r"(b[0]), "r"(b[1]));
}
__device__ __forceinline__ unsigned ford(float f) {
    unsigned u = __float_as_uint(f);
    return (u & 0x80000000u) ? ~u : (u | 0x80000000u);
}
__device__ __forceinline__ float funord(unsigned s) {
    return __uint_as_float((s & 0x80000000u) ? (s ^ 0x80000000u) : ~s);
}

// ---- prep: bake fragment-major hi/lo fp16 weight images (same layout) ----
__global__ void dtnet_prep(const float* __restrict__ W1, const float* __restrict__ b1,
                           const float* __restrict__ W2) {
    int idx = blockIdx.x * 256 + threadIdx.x;
    int lane = idx & 31, frag = idx >> 5;
    const int dd[4] = {0, 1, 8, 9};
    if (idx < 131072) {                       // W2 frags 0..4095: [s][kt][nt]
        int s = frag >> 9, kt = (frag >> 6) & 7, nt = frag & 63;
        int n = nt * 8 + (lane >> 2), k0 = kt * 16 + (lane & 3) * 2;
        float v[4];
        #pragma unroll
        for (int j = 0; j < 4; j++) {
            int kk = k0 + dd[j], g, c;
            if (kk < 64) { g = s * 64 + kk; c = g; }
            else         { g = s * 64 + kk - 64; c = 511 + g; }
            v[j] = (g < 511) ? W2[(size_t)n * 1022 + c] : 0.0f;
        }
        uint32_t h0, l0, h1, l1;
        sp2f(v[0], v[1], h0, l0); sp2f(v[2], v[3], h1, l1);
        *(uint4*)(g_w2f + (size_t)frag * 512 + lane * 16) = make_uint4(h0, h1, l0, l1);
    } else if (idx < 147456) {                // W1 frags 0..511: [s][kt][nt]
        int f2 = frag - 4096;
        int s = f2 >> 6, kt = (f2 >> 3) & 7, nt = f2 & 7;
        int g = s * 64 + nt * 8 + (lane >> 2), k0 = kt * 16 + (lane & 3) * 2;
        float v[4];
        #pragma unroll
        for (int j = 0; j < 4; j++)
            v[j] = (g < 511) ? W1[(size_t)g * 128 + k0 + dd[j]] : 0.0f;
        uint32_t h0, l0, h1, l1;
        sp2f(v[0], v[1], h0, l0); sp2f(v[2], v[3], h1, l1);
        *(uint4*)(g_w1f + (size_t)f2 * 512 + lane * 16) = make_uint4(h0, h1, l0, l1);
    }
    if (idx < 512) g_b1p[idx] = (idx < 511) ? b1[idx] : 0.0f;
}

// ---- main fused kernel ----
__global__ __launch_bounds__(256, 1)
void dtnet_mma(const float* __restrict__ x, const int* __restrict__ la,
               float* __restrict__ out) {
    extern __shared__ unsigned char smc[];
    const uint32_t sb = s2u(smc);
    const int tid = threadIdx.x, w = tid >> 5, lane = tid & 31;
    const int row0 = blockIdx.x * 64;
    unsigned* pool = (unsigned*)(smc + POOL_);
    const uint8_t* act = (const uint8_t*)(smc + ACT_);

    ((uint8_t*)(smc + ACT_))[tid] = (uint8_t)la[tid];
    ((uint8_t*)(smc + ACT_))[256 + tid] = (uint8_t)la[256 + tid];
    for (int i = tid; i < 1024; i += 256) pool[i] = 0u;

    // stage X [64 x 128] fp16-hi, swizzled 256B rows
    #pragma unroll
    for (int it = 0; it < 8; it++) {
        int idx = it * 256 + tid, r = idx >> 5, q = idx & 31;
        float4 v = ((const float4*)(x + (size_t)(row0 + r) * 128))[q];
        int kb = q >> 1;
        uint32_t off = r * 256 + ((kb & 8) | ((kb ^ r) & 7)) * 16 + (q & 1) * 8;
        *(uint2*)(smc + XH_ + off) = make_uint2(pk2(v.x, v.y), pk2(v.z, v.w));
    }
    __syncthreads();

    float acc[4][8][4];
    #pragma unroll
    for (int a = 0; a < 4; a++)
        #pragma unroll
        for (int b = 0; b < 8; b++)
            #pragma unroll
            for (int c = 0; c < 4; c++) acc[a][b][c] = 0.0f;

    for (int s = 0; s < 8; s++) {
        const uint32_t zbase = (s & 1) ? Z1_ : Z0_;
        // ---- phase 1: H(64 x 64) ----
        float hacc[4][4];
        #pragma unroll
        for (int a = 0; a < 4; a++)
            #pragma unroll
            for (int c = 0; c < 4; c++) hacc[a][c] = 0.0f;
        const int arow = (w & 3) * 16 + (lane & 7) + ((lane >> 3) & 1) * 8;
        #pragma unroll
        for (int kt = 0; kt < 8; kt++) {
            int cc = kt * 2 + (lane >> 4);
            uint32_t ao = arow * 256 + ((cc & 8) | ((cc ^ arow) & 7)) * 16;
            uint32_t ah[4];
            ldm4(ah, sb + XH_ + ao);
            uint4 t1[4];
            #pragma unroll
            for (int ntl = 0; ntl < 4; ntl++)
                t1[ntl] = *(const uint4*)(g_w1f +
                    ((size_t)((s * 8 + kt) * 8 + (w >> 2) * 4 + ntl) * 512 + lane * 16));
            #pragma unroll
            for (int ntl = 0; ntl < 4; ntl++) {
                uint32_t bh[2] = {t1[ntl].x, t1[ntl].y};
                mma(hacc[ntl], ah, bh);
            }
            #pragma unroll
            for (int ntl = 0; ntl < 4; ntl++) {
                uint32_t bl[2] = {t1[ntl].z, t1[ntl].w};
                mma(hacc[ntl], ah, bl);
            }
        }
        // bias + relu(+/-) -> fp16-hi Z smem (current buffer)
        #pragma unroll
        for (int ntl = 0; ntl < 4; ntl++) {
            int nt = (w >> 2) * 4 + ntl;
            int nloc = nt * 8 + (lane & 3) * 2, gn = s * 64 + nloc;
            float bb0 = g_b1p[gn], bb1 = g_b1p[gn + 1];
            #pragma unroll
            for (int rh = 0; rh < 2; rh++) {
                int row = (w & 3) * 16 + (lane >> 2) + rh * 8;
                float h0 = hacc[ntl][rh * 2] + bb0, h1 = hacc[ntl][rh * 2 + 1] + bb1;
                uint32_t off = row * 128 + (((nt ^ row) & 7) * 16) + (lane & 3) * 4;
                *(uint32_t*)(smc + zbase + off) =
                    pk2(fmaxf(h0, 0.f), fmaxf(h1, 0.f));            // zph
                *(uint32_t*)(smc + zbase + 8192 + off) =
                    pk2(fmaxf(-h0, 0.f), fmaxf(-h1, 0.f));          // zmh
            }
        }
        __syncthreads();   // single barrier per slab
        // ---- phase 2: acc += Z . W2slab^T (64 rows x 64 leaves/warp) ----
        #pragma unroll
        for (int kt = 0; kt < 8; kt++) {
            uint32_t zh = zbase + ((kt < 4) ? 0 : 8192);
            int ktl = kt & 3;
            uint4 tb[8];
            #pragma unroll
            for (int ntl = 0; ntl < 8; ntl++)
                tb[ntl] = *(const uint4*)(g_w2f +
                    ((size_t)((s * 8 + kt) * 64 + w * 8 + ntl) * 512 + lane * 16));
            int cc = ktl * 2 + (lane >> 4);
            #pragma unroll
            for (int mt = 0; mt < 4; mt++) {
                int row = mt * 16 + (lane & 7) + ((lane >> 3) & 1) * 8;
                uint32_t ao = row * 128 + (((cc ^ row) & 7) * 16);
                uint32_t ah[4];
                ldm4(ah, sb + zh + ao);
                #pragma unroll
                for (int ntl = 0; ntl < 8; ntl++) {
                    uint32_t bh[2] = {tb[ntl].x, tb[ntl].y};
                    mma(acc[mt][ntl], ah, bh);
                }
                #pragma unroll
                for (int ntl = 0; ntl < 8; ntl++) {
                    uint32_t bl[2] = {tb[ntl].z, tb[ntl].w};
                    mma(acc[mt][ntl], ah, bl);
                }
            }
        }
        // no trailing sync: next slab writes the other Z buffer
    }

    // ---- epilogue: segment-max + softmax ----
    #pragma unroll
    for (int mt = 0; mt < 4; mt++)
        #pragma unroll
        for (int ntl = 0; ntl < 8; ntl++)
            #pragma unroll
            for (int i = 0; i < 2; i++) {
                int col = w * 64 + ntl * 8 + (lane & 3) * 2 + i;
                int a = act[col];
                #pragma unroll
                for (int rh = 0; rh < 2; rh++) {
                    int row = mt * 16 + (lane >> 2) + rh * 8;
                    atomicMax(&pool[row * 16 + a], ford(acc[mt][ntl][rh * 2 + i]));
                }
            }
    __syncthreads();
    if (tid < 64) {
        float v[16], mx = -3.402823466e38f;
        #pragma unroll
        for (int a = 0; a < 16; a++) {
            v[a] = funord(pool[tid * 16 + a]);
            mx = fmaxf(mx, v[a]);
        }
        float sum = 0.f;
        #pragma unroll
        for (int a = 0; a < 16; a++) { v[a] = __expf(v[a] - mx); sum += v[a]; }
        float inv = 1.f / sum;
        float4* o = (float4*)(out + (size_t)(row0 + tid) * 16);
        o[0] = make_float4(v[0] * inv, v[1] * inv, v[2] * inv, v[3] * inv);
        o[1] = make_float4(v[4] * inv, v[5] * inv, v[6] * inv, v[7] * inv);
        o[2] = make_float4(v[8] * inv, v[9] * inv, v[10] * inv, v[11] * inv);
        o[3] = make_float4(v[12] * inv, v[13] * inv, v[14] * inv, v[15] * inv);
    }
}

extern "C" void kernel_launch(void* const* d_in, const int* in_sizes, int n_in,
                              void* d_out, int out_size) {
    const float* x  = (const float*)d_in[0];
    const float* W1 = (const float*)d_in[1];
    const float* b1 = (const float*)d_in[2];
    const float* W2 = (const float*)d_in[3];
    const int*   la = (const int*)d_in[4];
    float* out = (float*)d_out;

    dtnet_prep<<<576, 256>>>(W1, b1, W2);
    cudaFuncSetAttribute(dtnet_mma, cudaFuncAttributeMaxDynamicSharedMemorySize, SMEMB);
    int Btot = in_sizes[0] / 128;   // 131072
    dtnet_mma<<<Btot / 64, 256, SMEMB>>>(x, la, out);
}

// round 10
// speedup vs baseline: 6.6036x; 1.0201x over previous
#include <cuda_runtime.h>
#include <cuda_fp16.h>
#include <cstdint>

// B=131072, IN_DIM=128, N_NODES=511(pad 512), N_LEAVES=512, N_ACTIONS=16
// 64 rows/CTA, fp16 2-term: A(X,Z)=fp16 hi, B(W1,W2)=fp16 hi+lo
// Cross-slab pipeline: P1(s+1) issued before P2(s), one barrier per slab.
#define XH_   0
#define Z0_   16384          // zph 8KB @+0, zmh 8KB @+8192
#define Z1_   32768
#define ACT_  49152
#define POOL_ 49664
#define SMEMB (49664 + 4096)

__device__ __align__(16) unsigned char g_w2f[2097152]; // 4096 frag-blocks x 512B
__device__ __align__(16) unsigned char g_w1f[262144];  // 512 frag-blocks x 512B
__device__ float g_b1p[512];

__device__ __forceinline__ uint32_t s2u(const void* p) {
    uint32_t a;
    asm("{ .reg .u64 t; cvta.to.shared.u64 t, %1; cvt.u32.u64 %0, t; }" : "=r"(a) : "l"(p));
    return a;
}
__device__ __forceinline__ uint32_t pk2(float a, float b) {   // fp16 hi pack
    __half ah = __float2half_rn(a), bh = __float2half_rn(b);
    return (uint32_t)*(uint16_t*)&ah | ((uint32_t)*(uint16_t*)&bh << 16);
}
__device__ __forceinline__ void sp2f(float a, float b, uint32_t& h, uint32_t& l) {
    __half ah = __float2half_rn(a), bh = __float2half_rn(b);
    __half al = __float2half_rn(a - __half2float(ah));
    __half bl = __float2half_rn(b - __half2float(bh));
    h = (uint32_t)*(uint16_t*)&ah | ((uint32_t)*(uint16_t*)&bh << 16);
    l = (uint32_t)*(uint16_t*)&al | ((uint32_t)*(uint16_t*)&bl << 16);
}
__device__ __forceinline__ void ldm4(uint32_t* r, uint32_t a) {
    asm volatile("ldmatrix.sync.aligned.m8n8.x4.shared.b16 {%0,%1,%2,%3}, [%4];"
                 : "=r"(r[0]), "=r"(r[1]), "=r"(r[2]), "=r"(r[3]) : "r"(a));
}
__device__ __forceinline__ void mma(float* d, const uint32_t* a, const uint32_t* b) {
    asm volatile(
        "mma.sync.aligned.m16n8k16.row.col.f32.f16.f16.f32 "
        "{%0,%1,%2,%3}, {%4,%5,%6,%7}, {%8,%9}, {%0,%1,%2,%3};"
        : "+f"(d[0]), "+f"(d[1]), "+f"(d[2]), "+f"(d[3])
        : "r"(a[0]), "r"(a[1]), "r"(a[2]), "r"(a[3]), "r"(b[0]), "r"(b[1]));
}
__device__ __forceinline__ unsigned ford(float f) {
    unsigned u = __float_as_uint(f);
    return (u & 0x80000000u) ? ~u : (u | 0x80000000u);
}
__device__ __forceinline__ float funord(unsigned s) {
    return __uint_as_float((s & 0x80000000u) ? (s ^ 0x80000000u) : ~s);
}

// ---- prep: bake fragment-major hi/lo fp16 weight images (same layout) ----
__global__ void dtnet_prep(const float* __restrict__ W1, const float* __restrict__ b1,
                           const float* __restrict__ W2) {
    int idx = blockIdx.x * 256 + threadIdx.x;
    int lane = idx & 31, frag = idx >> 5;
    const int dd[4] = {0, 1, 8, 9};
    if (idx < 131072) {                       // W2 frags 0..4095: [s][kt][nt]
        int s = frag >> 9, kt = (frag >> 6) & 7, nt = frag & 63;
        int n = nt * 8 + (lane >> 2), k0 = kt * 16 + (lane & 3) * 2;
        float v[4];
        #pragma unroll
        for (int j = 0; j < 4; j++) {
            int kk = k0 + dd[j], g, c;
            if (kk < 64) { g = s * 64 + kk; c = g; }
            else         { g = s * 64 + kk - 64; c = 511 + g; }
            v[j] = (g < 511) ? W2[(size_t)n * 1022 + c] : 0.0f;
        }
        uint32_t h0, l0, h1, l1;
        sp2f(v[0], v[1], h0, l0); sp2f(v[2], v[3], h1, l1);
        *(uint4*)(g_w2f + (size_t)frag * 512 + lane * 16) = make_uint4(h0, h1, l0, l1);
    } else if (idx < 147456) {                // W1 frags 0..511: [s][kt][nt]
        int f2 = frag - 4096;
        int s = f2 >> 6, kt = (f2 >> 3) & 7, nt = f2 & 7;
        int g = s * 64 + nt * 8 + (lane >> 2), k0 = kt * 16 + (lane & 3) * 2;
        float v[4];
        #pragma unroll
        for (int j = 0; j < 4; j++)
            v[j] = (g < 511) ? W1[(size_t)g * 128 + k0 + dd[j]] : 0.0f;
        uint32_t h0, l0, h1, l1;
        sp2f(v[0], v[1], h0, l0); sp2f(v[2], v[3], h1, l1);
        *(uint4*)(g_w1f + (size_t)f2 * 512 + lane * 16) = make_uint4(h0, h1, l0, l1);
    }
    if (idx < 512) g_b1p[idx] = (idx < 511) ? b1[idx] : 0.0f;
}

// ---- phase 1: H(64x64) for slab s -> relu(+/-) fp16 into Z buffer ----
__device__ __forceinline__ void phase1(unsigned char* smc, uint32_t sb, int s,
                                       int w, int lane, uint32_t zbase) {
    float hacc[4][4];
    #pragma unroll
    for (int a = 0; a < 4; a++)
        #pragma unroll
        for (int c = 0; c < 4; c++) hacc[a][c] = 0.0f;
    const int arow = (w & 3) * 16 + (lane & 7) + ((lane >> 3) & 1) * 8;
    #pragma unroll
    for (int kt = 0; kt < 8; kt++) {
        int cc = kt * 2 + (lane >> 4);
        uint32_t ao = arow * 256 + ((cc & 8) | ((cc ^ arow) & 7)) * 16;
        uint32_t ah[4];
        ldm4(ah, sb + XH_ + ao);
        uint4 t1[4];
        #pragma unroll
        for (int ntl = 0; ntl < 4; ntl++)
            t1[ntl] = *(const uint4*)(g_w1f +
                ((size_t)((s * 8 + kt) * 8 + (w >> 2) * 4 + ntl) * 512 + lane * 16));
        #pragma unroll
        for (int ntl = 0; ntl < 4; ntl++) {
            uint32_t bh[2] = {t1[ntl].x, t1[ntl].y};
            mma(hacc[ntl], ah, bh);
        }
        #pragma unroll
        for (int ntl = 0; ntl < 4; ntl++) {
            uint32_t bl[2] = {t1[ntl].z, t1[ntl].w};
            mma(hacc[ntl], ah, bl);
        }
    }
    #pragma unroll
    for (int ntl = 0; ntl < 4; ntl++) {
        int nt = (w >> 2) * 4 + ntl;
        int nloc = nt * 8 + (lane & 3) * 2, gn = s * 64 + nloc;
        float bb0 = g_b1p[gn], bb1 = g_b1p[gn + 1];
        #pragma unroll
        for (int rh = 0; rh < 2; rh++) {
            int row = (w & 3) * 16 + (lane >> 2) + rh * 8;
            float h0 = hacc[ntl][rh * 2] + bb0, h1 = hacc[ntl][rh * 2 + 1] + bb1;
            uint32_t off = row * 128 + (((nt ^ row) & 7) * 16) + (lane & 3) * 4;
            *(uint32_t*)(smc + zbase + off) =
                pk2(fmaxf(h0, 0.f), fmaxf(h1, 0.f));            // zph
            *(uint32_t*)(smc + zbase + 8192 + off) =
                pk2(fmaxf(-h0, 0.f), fmaxf(-h1, 0.f));          // zmh
        }
    }
}

// ---- phase 2: acc += Z(s) . W2slab^T ----
__device__ __forceinline__ void phase2(unsigned char* smc, uint32_t sb, int s,
                                       int w, int lane, uint32_t zbase,
                                       float acc[4][8][4]) {
    #pragma unroll
    for (int kt = 0; kt < 8; kt++) {
        uint32_t zh = zbase + ((kt < 4) ? 0 : 8192);
        int ktl = kt & 3;
        uint4 tb[8];
        #pragma unroll
        for (int ntl = 0; ntl < 8; ntl++)
            tb[ntl] = *(const uint4*)(g_w2f +
                ((size_t)((s * 8 + kt) * 64 + w * 8 + ntl) * 512 + lane * 16));
        int cc = ktl * 2 + (lane >> 4);
        #pragma unroll
        for (int mt = 0; mt < 4; mt++) {
            int row = mt * 16 + (lane & 7) + ((lane >> 3) & 1) * 8;
            uint32_t ao = row * 128 + (((cc ^ row) & 7) * 16);
            uint32_t ah[4];
            ldm4(ah, sb + zh + ao);
            #pragma unroll
            for (int ntl = 0; ntl < 8; ntl++) {
                uint32_t bh[2] = {tb[ntl].x, tb[ntl].y};
                mma(acc[mt][ntl], ah, bh);
            }
            #pragma unroll
            for (int ntl = 0; ntl < 8; ntl++) {
                uint32_t bl[2] = {tb[ntl].z, tb[ntl].w};
                mma(acc[mt][ntl], ah, bl);
            }
        }
    }
}

// ---- main fused kernel ----
__global__ __launch_bounds__(256, 1)
void dtnet_mma(const float* __restrict__ x, const int* __restrict__ la,
               float* __restrict__ out) {
    extern __shared__ unsigned char smc[];
    const uint32_t sb = s2u(smc);
    const int tid = threadIdx.x, w = tid >> 5, lane = tid & 31;
    const int row0 = blockIdx.x * 64;
    unsigned* pool = (unsigned*)(smc + POOL_);
    const uint8_t* act = (const uint8_t*)(smc + ACT_);

    ((uint8_t*)(smc + ACT_))[tid] = (uint8_t)la[tid];
    ((uint8_t*)(smc + ACT_))[256 + tid] = (uint8_t)la[256 + tid];
    for (int i = tid; i < 1024; i += 256) pool[i] = 0u;

    // stage X [64 x 128] fp16-hi, swizzled 256B rows
    #pragma unroll
    for (int it = 0; it < 8; it++) {
        int idx = it * 256 + tid, r = idx >> 5, q = idx & 31;
        float4 v = ((const float4*)(x + (size_t)(row0 + r) * 128))[q];
        int kb = q >> 1;
        uint32_t off = r * 256 + ((kb & 8) | ((kb ^ r) & 7)) * 16 + (q & 1) * 8;
        *(uint2*)(smc + XH_ + off) = make_uint2(pk2(v.x, v.y), pk2(v.z, v.w));
    }
    __syncthreads();

    float acc[4][8][4];
    #pragma unroll
    for (int a = 0; a < 4; a++)
        #pragma unroll
        for (int b = 0; b < 8; b++)
            #pragma unroll
            for (int c = 0; c < 4; c++) acc[a][b][c] = 0.0f;

    // prologue: P1(0) into buf0
    phase1(smc, sb, 0, w, lane, Z0_);
    __syncthreads();

    #pragma unroll 2
    for (int s = 0; s < 8; s++) {
        // P1(s+1) into the other buffer, overlapped with P2(s)
        if (s < 7)
            phase1(smc, sb, s + 1, w, lane, ((s + 1) & 1) ? Z1_ : Z0_);
        phase2(smc, sb, s, w, lane, (s & 1) ? Z1_ : Z0_, acc);
        __syncthreads();
    }

    // ---- epilogue: segment-max + softmax ----
    #pragma unroll
    for (int mt = 0; mt < 4; mt++)
        #pragma unroll
        for (int ntl = 0; ntl < 8; ntl++)
            #pragma unroll
            for (int i = 0; i < 2; i++) {
                int col = w * 64 + ntl * 8 + (lane & 3) * 2 + i;
                int a = act[col];
                #pragma unroll
                for (int rh = 0; rh < 2; rh++) {
                    int row = mt * 16 + (lane >> 2) + rh * 8;
                    atomicMax(&pool[row * 16 + a], ford(acc[mt][ntl][rh * 2 + i]));
                }
            }
    __syncthreads();
    if (tid < 64) {
        float v[16], mx = -3.402823466e38f;
        #pragma unroll
        for (int a = 0; a < 16; a++) {
            v[a] = funord(pool[tid * 16 + a]);
            mx = fmaxf(mx, v[a]);
        }
        float sum = 0.f;
        #pragma unroll
        for (int a = 0; a < 16; a++) { v[a] = __expf(v[a] - mx); sum += v[a]; }
        float inv = 1.f / sum;
        float4* o = (float4*)(out + (size_t)(row0 + tid) * 16);
        o[0] = make_float4(v[0] * inv, v[1] * inv, v[2] * inv, v[3] * inv);
        o[1] = make_float4(v[4] * inv, v[5] * inv, v[6] * inv, v[7] * inv);
        o[2] = make_float4(v[8] * inv, v[9] * inv, v[10] * inv, v[11] * inv);
        o[3] = make_float4(v[12] * inv, v[13] * inv, v[14] * inv, v[15] * inv);
    }
}

extern "C" void kernel_launch(void* const* d_in, const int* in_sizes, int n_in,
                              void* d_out, int out_size) {
    const float* x  = (const float*)d_in[0];
    const float* W1 = (const float*)d_in[1];
    const float* b1 = (const float*)d_in[2];
    const float* W2 = (const float*)d_in[3];
    const int*   la = (const int*)d_in[4];
    float* out = (float*)d_out;

    dtnet_prep<<<576, 256>>>(W1, b1, W2);
    cudaFuncSetAttribute(dtnet_mma, cudaFuncAttributeMaxDynamicSharedMemorySize, SMEMB);
    int Btot = in_sizes[0] / 128;   // 131072
    dtnet_mma<<<Btot / 64, 256, SMEMB>>>(x, la, out);
}

// round 11
// speedup vs baseline: 8.0996x; 1.2266x over previous
#include <cuda_runtime.h>
#include <cuda_fp16.h>
#include <cstdint>

// B=131072, IN_DIM=128, N_NODES=511(pad 512), N_LEAVES=512, N_ACTIONS=16
// 64 rows/CTA. P1 dense fp16 (W1 hi+lo). P2 sparse 2:4 mma.sp m16n8k32:
// A = |h| (stored values), metadata from sign(h), B = W2 interleaved [+,-] cols.
#define XH_   0
#define Z0_   16384     // |h| 8KB @+0, sign bytes 4KB @+8192
#define Z1_   28672
#define ACT_  40960
#define POOL_ 41472
#define SMEMB 45568

__device__ __align__(16) unsigned char g_w2f[2097152]; // 2048 sparse-B frags x 1KB
__device__ __align__(16) unsigned char g_w1f[262144];  // 512 frag-blocks x 512B
__device__ float g_b1p[512];

__device__ __forceinline__ uint32_t s2u(const void* p) {
    uint32_t a;
    asm("{ .reg .u64 t; cvta.to.shared.u64 t, %1; cvt.u32.u64 %0, t; }" : "=r"(a) : "l"(p));
    return a;
}
__device__ __forceinline__ uint32_t pk2(float a, float b) {
    __half ah = __float2half_rn(a), bh = __float2half_rn(b);
    return (uint32_t)*(uint16_t*)&ah | ((uint32_t)*(uint16_t*)&bh << 16);
}
__device__ __forceinline__ void sp2f(float a, float b, uint32_t& h, uint32_t& l) {
    __half ah = __float2half_rn(a), bh = __float2half_rn(b);
    __half al = __float2half_rn(a - __half2float(ah));
    __half bl = __float2half_rn(b - __half2float(bh));
    h = (uint32_t)*(uint16_t*)&ah | ((uint32_t)*(uint16_t*)&bh << 16);
    l = (uint32_t)*(uint16_t*)&al | ((uint32_t)*(uint16_t*)&bl << 16);
}
__device__ __forceinline__ void ldm4(uint32_t* r, uint32_t a) {
    asm volatile("ldmatrix.sync.aligned.m8n8.x4.shared.b16 {%0,%1,%2,%3}, [%4];"
                 : "=r"(r[0]), "=r"(r[1]), "=r"(r[2]), "=r"(r[3]) : "r"(a));
}
__device__ __forceinline__ void mma(float* d, const uint32_t* a, const uint32_t* b) {
    asm volatile(
        "mma.sync.aligned.m16n8k16.row.col.f32.f16.f16.f32 "
        "{%0,%1,%2,%3}, {%4,%5,%6,%7}, {%8,%9}, {%0,%1,%2,%3};"
        : "+f"(d[0]), "+f"(d[1]), "+f"(d[2]), "+f"(d[3])
        : "r"(a[0]), "r"(a[1]), "r"(a[2]), "r"(a[3]), "r"(b[0]), "r"(b[1]));
}
__device__ __forceinline__ void mma_sp(float* d, const uint32_t* a, const uint4 b,
                                       uint32_t e) {
    asm volatile(
        "mma.sp::ordered_metadata.sync.aligned.m16n8k32.row.col.f32.f16.f16.f32 "
        "{%0,%1,%2,%3}, {%4,%5,%6,%7}, {%8,%9,%10,%11}, {%0,%1,%2,%3}, %12, 0x0;"
        : "+f"(d[0]), "+f"(d[1]), "+f"(d[2]), "+f"(d[3])
        : "r"(a[0]), "r"(a[1]), "r"(a[2]), "r"(a[3]),
          "r"(b.x), "r"(b.y), "r"(b.z), "r"(b.w), "r"(e));
}
// 8 sign bytes (two u32, each byte 0/1) -> 16-bit metadata (4 nibbles):
// nibble g = s_{2g} | (2+s_{2g+1})<<2
__device__ __forceinline__ uint32_t exp16(uint32_t x0, uint32_t x1) {
    uint32_t m0 = (x0 | (x0 >> 6) | (x0 >> 12) | (x0 >> 18)) & 0xFFu;
    uint32_t m1 = (x1 | (x1 >> 6) | (x1 >> 12) | (x1 >> 18)) & 0xFFu;
    return 0x8888u | m0 | (m1 << 8);
}
__device__ __forceinline__ unsigned ford(float f) {
    unsigned u = __float_as_uint(f);
    return (u & 0x80000000u) ? ~u : (u | 0x80000000u);
}
__device__ __forceinline__ float funord(unsigned s) {
    return __uint_as_float((s & 0x80000000u) ? (s ^ 0x80000000u) : ~s);
}

// ---- prep: W1 dense frags (unchanged); W2 sparse-B frags (k32 interleaved) ----
__global__ void dtnet_prep(const float* __restrict__ W1, const float* __restrict__ b1,
                           const float* __restrict__ W2) {
    int idx = blockIdx.x * 256 + threadIdx.x;
    int lane = idx & 31;
    if (idx < 65536) {            // W2 sparse frags 0..2047: [s][ks][nt], 1KB each
        int frag = idx >> 5;
        int s = frag >> 8, ks = (frag >> 6) & 3, nt = frag & 63;
        int l = nt * 8 + (lane >> 2);
        uint32_t hw[4], lw[4];
        #pragma unroll
        for (int i = 0; i < 4; i++) {
            int k0 = i * 8 + (lane & 3) * 2;
            float v[2];
            #pragma unroll
            for (int j = 0; j < 2; j++) {
                int k = k0 + j;
                int n = s * 64 + ks * 16 + (k >> 1);
                int c = (k & 1) ? (511 + n) : n;
                v[j] = (n < 511) ? W2[(size_t)l * 1022 + c] : 0.0f;
            }
            sp2f(v[0], v[1], hw[i], lw[i]);
        }
        *(uint4*)(g_w2f + (size_t)frag * 1024 + lane * 16) =
            make_uint4(hw[0], hw[1], hw[2], hw[3]);
        *(uint4*)(g_w2f + (size_t)frag * 1024 + 512 + lane * 16) =
            make_uint4(lw[0], lw[1], lw[2], lw[3]);
    } else if (idx < 81920) {     // W1 frags 0..511 (layout unchanged)
        int f2 = (idx >> 5) - 2048;
        int s = f2 >> 6, kt = (f2 >> 3) & 7, nt = f2 & 7;
        int g = s * 64 + nt * 8 + (lane >> 2), k0 = kt * 16 + (lane & 3) * 2;
        const int dd[4] = {0, 1, 8, 9};
        float v[4];
        #pragma unroll
        for (int j = 0; j < 4; j++)
            v[j] = (g < 511) ? W1[(size_t)g * 128 + k0 + dd[j]] : 0.0f;
        uint32_t h0, l0, h1, l1;
        sp2f(v[0], v[1], h0, l0); sp2f(v[2], v[3], h1, l1);
        *(uint4*)(g_w1f + (size_t)f2 * 512 + lane * 16) = make_uint4(h0, h1, l0, l1);
    }
    if (idx < 512) g_b1p[idx] = (idx < 511) ? b1[idx] : 0.0f;
}

// ---- phase 1: H(64x64) slab s -> |h| fp16 + sign bytes into Z buffer ----
__device__ __forceinline__ void phase1(unsigned char* smc, uint32_t sb, int s,
                                       int w, int lane, uint32_t zbase) {
    float hacc[4][4];
    #pragma unroll
    for (int a = 0; a < 4; a++)
        #pragma unroll
        for (int c = 0; c < 4; c++) hacc[a][c] = 0.0f;
    const int arow = (w & 3) * 16 + (lane & 7) + ((lane >> 3) & 1) * 8;
    #pragma unroll
    for (int kt = 0; kt < 8; kt++) {
        int cc = kt * 2 + (lane >> 4);
        uint32_t ao = arow * 256 + ((cc & 8) | ((cc ^ arow) & 7)) * 16;
        uint32_t ah[4];
        ldm4(ah, sb + XH_ + ao);
        uint4 t1[4];
        #pragma unroll
        for (int ntl = 0; ntl < 4; ntl++)
            t1[ntl] = *(const uint4*)(g_w1f +
                ((size_t)((s * 8 + kt) * 8 + (w >> 2) * 4 + ntl) * 512 + lane * 16));
        #pragma unroll
        for (int ntl = 0; ntl < 4; ntl++) {
            uint32_t bh[2] = {t1[ntl].x, t1[ntl].y};
            mma(hacc[ntl], ah, bh);
        }
        #pragma unroll
        for (int ntl = 0; ntl < 4; ntl++) {
            uint32_t bl[2] = {t1[ntl].z, t1[ntl].w};
            mma(hacc[ntl], ah, bl);
        }
    }
    #pragma unroll
    for (int ntl = 0; ntl < 4; ntl++) {
        int nt = (w >> 2) * 4 + ntl;
        int nloc = nt * 8 + (lane & 3) * 2, gn = s * 64 + nloc;
        float bb0 = g_b1p[gn], bb1 = g_b1p[gn + 1];
        #pragma unroll
        for (int rh = 0; rh < 2; rh++) {
            int row = (w & 3) * 16 + (lane >> 2) + rh * 8;
            float h0 = hacc[ntl][rh * 2] + bb0, h1 = hacc[ntl][rh * 2 + 1] + bb1;
            uint32_t off = row * 128 + (((nt ^ row) & 7) * 16) + (lane & 3) * 4;
            *(uint32_t*)(smc + zbase + off) = pk2(fabsf(h0), fabsf(h1));
            uint32_t s0 = __float_as_uint(h0) >> 31, s1 = __float_as_uint(h1) >> 31;
            *(uint16_t*)(smc + zbase + 8192 + row * 64 + nloc) =
                (uint16_t)(s0 | (s1 << 8));
        }
    }
}

// ---- phase 2 (sparse): acc += Z(s) . W2slab^T, 2:4 metadata from signs ----
__device__ __forceinline__ void phase2(unsigned char* smc, uint32_t sb, int s,
                                       int w, int lane, uint32_t zbase,
                                       float acc[4][8][4]) {
    const int quad = lane >> 2, kh = lane & 1;
    const uint32_t sgn = zbase + 8192;
    #pragma unroll
    for (int ks = 0; ks < 4; ks++) {
        uint32_t a[4][4], e[4];
        int cc = ks * 2 + (lane >> 4);
        #pragma unroll
        for (int mt = 0; mt < 4; mt++) {
            int row = mt * 16 + (lane & 7) + ((lane >> 3) & 1) * 8;
            uint32_t ao = row * 128 + (((cc ^ row) & 7) * 16);
            ldm4(a[mt], sb + zbase + ao);
            int r0 = mt * 16 + quad;
            uint2 sA = *(const uint2*)(smc + sgn + r0 * 64 + ks * 16 + kh * 8);
            uint2 sB = *(const uint2*)(smc + sgn + (r0 + 8) * 64 + ks * 16 + kh * 8);
            e[mt] = exp16(sA.x, sA.y) | (exp16(sB.x, sB.y) << 16);
        }
        uint4 tb[8];
        #pragma unroll
        for (int ntl = 0; ntl < 8; ntl++)
            tb[ntl] = *(const uint4*)(g_w2f +
                ((size_t)((s * 4 + ks) * 64 + w * 8 + ntl) * 1024 + lane * 16));
        #pragma unroll
        for (int mt = 0; mt < 4; mt++)
            #pragma unroll
            for (int ntl = 0; ntl < 8; ntl++)
                mma_sp(acc[mt][ntl], a[mt], tb[ntl], e[mt]);
        #pragma unroll
        for (int ntl = 0; ntl < 8; ntl++)
            tb[ntl] = *(const uint4*)(g_w2f +
                ((size_t)((s * 4 + ks) * 64 + w * 8 + ntl) * 1024 + 512 + lane * 16));
        #pragma unroll
        for (int mt = 0; mt < 4; mt++)
            #pragma unroll
            for (int ntl = 0; ntl < 8; ntl++)
                mma_sp(acc[mt][ntl], a[mt], tb[ntl], e[mt]);
    }
}

// ---- main fused kernel ----
__global__ __launch_bounds__(256, 1)
void dtnet_mma(const float* __restrict__ x, const int* __restrict__ la,
               float* __restrict__ out) {
    extern __shared__ unsigned char smc[];
    const uint32_t sb = s2u(smc);
    const int tid = threadIdx.x, w = tid >> 5, lane = tid & 31;
    const int row0 = blockIdx.x * 64;
    unsigned* pool = (unsigned*)(smc + POOL_);
    const uint8_t* act = (const uint8_t*)(smc + ACT_);

    ((uint8_t*)(smc + ACT_))[tid] = (uint8_t)la[tid];
    ((uint8_t*)(smc + ACT_))[256 + tid] = (uint8_t)la[256 + tid];
    for (int i = tid; i < 1024; i += 256) pool[i] = 0u;

    // stage X [64 x 128] fp16-hi, swizzled 256B rows
    #pragma unroll
    for (int it = 0; it < 8; it++) {
        int idx = it * 256 + tid, r = idx >> 5, q = idx & 31;
        float4 v = ((const float4*)(x + (size_t)(row0 + r) * 128))[q];
        int kb = q >> 1;
        uint32_t off = r * 256 + ((kb & 8) | ((kb ^ r) & 7)) * 16 + (q & 1) * 8;
        *(uint2*)(smc + XH_ + off) = make_uint2(pk2(v.x, v.y), pk2(v.z, v.w));
    }
    __syncthreads();

    float acc[4][8][4];
    #pragma unroll
    for (int a = 0; a < 4; a++)
        #pragma unroll
        for (int b = 0; b < 8; b++)
            #pragma unroll
            for (int c = 0; c < 4; c++) acc[a][b][c] = 0.0f;

    phase1(smc, sb, 0, w, lane, Z0_);
    __syncthreads();

    #pragma unroll 2
    for (int s = 0; s < 8; s++) {
        if (s < 7)
            phase1(smc, sb, s + 1, w, lane, ((s + 1) & 1) ? Z1_ : Z0_);
        phase2(smc, sb, s, w, lane, (s & 1) ? Z1_ : Z0_, acc);
        __syncthreads();
    }

    // ---- epilogue: segment-max + softmax ----
    #pragma unroll
    for (int mt = 0; mt < 4; mt++)
        #pragma unroll
        for (int ntl = 0; ntl < 8; ntl++)
            #pragma unroll
            for (int i = 0; i < 2; i++) {
                int col = w * 64 + ntl * 8 + (lane & 3) * 2 + i;
                int a = act[col];
                #pragma unroll
                for (int rh = 0; rh < 2; rh++) {
                    int row = mt * 16 + (lane >> 2) + rh * 8;
                    atomicMax(&pool[row * 16 + a], ford(acc[mt][ntl][rh * 2 + i]));
                }
            }
    __syncthreads();
    if (tid < 64) {
        float v[16], mx = -3.402823466e38f;
        #pragma unroll
        for (int a = 0; a < 16; a++) {
            v[a] = funord(pool[tid * 16 + a]);
            mx = fmaxf(mx, v[a]);
        }
        float sum = 0.f;
        #pragma unroll
        for (int a = 0; a < 16; a++) { v[a] = __expf(v[a] - mx); sum += v[a]; }
        float inv = 1.f / sum;
        float4* o = (float4*)(out + (size_t)(row0 + tid) * 16);
        o[0] = make_float4(v[0] * inv, v[1] * inv, v[2] * inv, v[3] * inv);
        o[1] = make_float4(v[4] * inv, v[5] * inv, v[6] * inv, v[7] * inv);
        o[2] = make_float4(v[8] * inv, v[9] * inv, v[10] * inv, v[11] * inv);
        o[3] = make_float4(v[12] * inv, v[13] * inv, v[14] * inv, v[15] * inv);
    }
}

extern "C" void kernel_launch(void* const* d_in, const int* in_sizes, int n_in,
                              void* d_out, int out_size) {
    const float* x  = (const float*)d_in[0];
    const float* W1 = (const float*)d_in[1];
    const float* b1 = (const float*)d_in[2];
    const float* W2 = (const float*)d_in[3];
    const int*   la = (const int*)d_in[4];
    float* out = (float*)d_out;

    dtnet_prep<<<320, 256>>>(W1, b1, W2);
    cudaFuncSetAttribute(dtnet_mma, cudaFuncAttributeMaxDynamicSharedMemorySize, SMEMB);
    int Btot = in_sizes[0] / 128;   // 131072
    dtnet_mma<<<Btot / 64, 256, SMEMB>>>(x, la, out);
}